// round 16
// baseline (speedup 1.0000x reference)
#include <cuda_runtime.h>
#include <cstdint>

// CRF forward (logZ) + Viterbi, SPLIT into two warps per block (same batch):
// warp0 = forward, warp1 = viterbi. Scan bodies are verbatim R15 (351us,
// rel_err 2.5e-6): amortized power-of-2 renorm forward (no shfl on even
// steps, no fv0 shfl ever), exact fmax-tree + eq-bitmap first-index argmax.
// Rationale: R15 per-warp IPC = 0.25 (issue 42.7% @ 1.73 warps/SMSP) —
// doubling resident warps lets the arbiter cover intra-warp stalls. Earlier
// split failures are explained: R5 = heavy fwd chain, R8 = register spills
// (tr[32]/vv[32] at 96 regs). This version is register-lean like R15.
// out (f32): [0,B) logZ, [B,2B) best_score, [2B, 2B+S*B*T) pointers.

constexpr int S = 1024, B = 1024, T = 32;
#define NEG_INF   (-10000.0f)
#define START_TAG 29
#define STOP_TAG  30

__device__ __forceinline__ void ffma2(unsigned long long& d, unsigned long long a, unsigned long long b) {
    asm("fma.rn.f32x2 %0, %1, %2, %0;" : "+l"(d) : "l"(a), "l"(b));
}
__device__ __forceinline__ unsigned long long fadd2(unsigned long long a, unsigned long long b) {
    unsigned long long r;
    asm("add.rn.f32x2 %0, %1, %2;" : "=l"(r) : "l"(a), "l"(b));
    return r;
}
__device__ __forceinline__ unsigned long long pack2(float lo, float hi) {
    unsigned long long r;
    asm("mov.b64 %0, {%1, %2};" : "=l"(r) : "f"(lo), "f"(hi));
    return r;
}
__device__ __forceinline__ void unpack2(unsigned long long v, float& lo, float& hi) {
    asm("mov.b64 {%0, %1}, %2;" : "=f"(lo), "=f"(hi) : "l"(v));
}

__global__ void __launch_bounds__(64) crf_kernel(
    const float* __restrict__ feats, const float* __restrict__ mask,
    const float* __restrict__ trans, float* __restrict__ out)
{
    __shared__ __align__(16) float Eb[2][T];   // forward exp-state (warp 0)
    __shared__ __align__(16) float Sb[2][T];   // viterbi scores    (warp 1)

    const int lane = threadIdx.x & 31;
    const int warp = threadIdx.x >> 5;
    const int b    = blockIdx.x;

    // length = first s with mask[s][b]==0 (mask monotone). One-time search.
    int lo = 0, hi = S;
    #pragma unroll 1
    while (lo < hi) {
        const int mid = (lo + hi) >> 1;
        if (__ldg(mask + (size_t)mid * B + b) != 0.0f) lo = mid + 1; else hi = mid;
    }
    const int len = lo;

    const float L2E = 1.4426950408889634f;
    const float LN2 = 0.6931471805599453f;
    const float tstop = __ldg(trans + STOP_TAG * T + lane);

    const size_t BT = (size_t)B * T;
    const float* fp = feats + (size_t)b * T + lane;

    // Depth-4 register prefetch ring (shared pattern, per-warp instance).
    float fq[4];
    #pragma unroll
    for (int k = 0; k < 4; k++) fq[k] = __ldg(fp + (size_t)k * BT);

    if (warp == 0) {
        // ================= Forward: log partition (R15 verbatim) =================
        unsigned long long W2[T / 2];
        #pragma unroll
        for (int k = 0; k < T / 2; k++)
            W2[k] = pack2(__expf(__ldg(trans + lane * T + 2 * k)),
                          __expf(__ldg(trans + lane * T + 2 * k + 1)));

        float Ev = (lane == START_TAG) ? 1.0f : 0.0f;
        float O  = 0.0f;

        Eb[0][lane] = Ev;
        __syncwarp();

        #pragma unroll 4
        for (int s = 0; s < len; s++) {
            const int j  = s & 3;
            const int pb = s & 1;
            const float fv = fq[j];
            const int pfr = (s + 4 < S) ? (s + 4) : (S - 1);
            fq[j] = __ldg(fp + (size_t)pfr * BT);

            float X;                                 // exp(feat) raw
            asm("ex2.approx.ftz.f32 %0, %1;" : "=f"(X) : "f"(fv * L2E));

            const ulonglong2* e2 = (const ulonglong2*)Eb[pb];
            unsigned long long a0 = 0ull, a1 = 0ull, a2 = 0ull, a3 = 0ull;
            #pragma unroll
            for (int k = 0; k < 4; k++) {
                const ulonglong2 qa = e2[2 * k];
                const ulonglong2 qb = e2[2 * k + 1];
                ffma2(a0, qa.x, W2[4 * k]);
                ffma2(a1, qa.y, W2[4 * k + 1]);
                ffma2(a2, qb.x, W2[4 * k + 2]);
                ffma2(a3, qb.y, W2[4 * k + 3]);
            }
            const unsigned long long sAB = fadd2(fadd2(a0, a1), fadd2(a2, a3));
            float sl, sh; unpack2(sAB, sl, sh);
            const float sum = sl + sh;

            if (pb) {
                // Odd step: exact power-of-2 renorm off lane0's sum exponent.
                const int s0b = __shfl_sync(0xffffffffu, __float_as_int(sum), 0);
                const int e   = (s0b >> 23) - 127;
                const float g = __int_as_float((127 - e) << 23);  // exact 2^-e
                Ev = (sum * g) * X;
                O = fmaf((float)e, LN2, O);
            } else {
                Ev = sum * X;                        // no cross-lane traffic
            }

            Eb[pb ^ 1][lane] = Ev;
            __syncwarp();
        }

        // logZ = O + log( sum_i E_i * exp(tstop_i) )
        float z = Ev * __expf(tstop);
        #pragma unroll
        for (int o = 16; o; o >>= 1)
            z += __shfl_xor_sync(0xffffffffu, z, o);
        if (lane == 0) out[b] = O + __logf(z);
    } else {
        // ================= Viterbi: max score + pointers (R15 verbatim) =================
        unsigned long long T2[T / 2];
        #pragma unroll
        for (int k = 0; k < T / 2; k++)
            T2[k] = pack2(__ldg(trans + lane * T + 2 * k),
                          __ldg(trans + lane * T + 2 * k + 1));

        float sc = (lane == START_TAG) ? 0.0f : NEG_INF;
        Sb[0][lane] = sc;
        __syncwarp();

        float* pout = out + 2 * B + (size_t)b * T + lane;

        #pragma unroll 4
        for (int s = 0; s < len; s++) {
            const int j  = s & 3;
            const int pb = s & 1;
            const float fv = fq[j];
            const int pfr = (s + 4 < S) ? (s + 4) : (S - 1);
            fq[j] = __ldg(fp + (size_t)pfr * BT);

            const ulonglong2* s2 = (const ulonglong2*)Sb[pb];
            float vv[T];
            #pragma unroll
            for (int k = 0; k < 8; k++) {
                const ulonglong2 q = s2[k];
                float x0, x1, y0, y1;
                unpack2(fadd2(q.x, T2[2 * k]),     x0, x1);
                unpack2(fadd2(q.y, T2[2 * k + 1]), y0, y1);
                vv[4 * k]     = x0; vv[4 * k + 1] = x1;
                vv[4 * k + 2] = y0; vv[4 * k + 3] = y1;
            }
            float mx[16];
            #pragma unroll
            for (int i = 0; i < 16; i++) mx[i] = fmaxf(vv[i], vv[i + 16]);
            #pragma unroll
            for (int off = 8; off; off >>= 1)
                #pragma unroll
                for (int i = 0; i < 8; i++)
                    if (i < off) mx[i] = fmaxf(mx[i], mx[i + off]);
            const float vmax = mx[0];
            sc = vmax + fv;                          // exact update

            Sb[pb ^ 1][lane] = sc;
            __syncwarp();

            // off-chain: EXACT first-index argmax + pointer store
            unsigned eq = 0;
            #pragma unroll
            for (int h = 0; h < T; h++)
                if (vv[h] == vmax) eq |= (1u << h);
            __stcs(pout, (float)(__ffs(eq) - 1));
            pout += BT;
        }

        if (len < S) {
            // Frozen scores: Sb[len&1] holds final sc. One more argmax = tail ptr.
            const ulonglong2* s2 = (const ulonglong2*)Sb[len & 1];
            float vv[T];
            #pragma unroll
            for (int k = 0; k < 8; k++) {
                const ulonglong2 q = s2[k];
                float x0, x1, y0, y1;
                unpack2(fadd2(q.x, T2[2 * k]),     x0, x1);
                unpack2(fadd2(q.y, T2[2 * k + 1]), y0, y1);
                vv[4 * k]     = x0; vv[4 * k + 1] = x1;
                vv[4 * k + 2] = y0; vv[4 * k + 3] = y1;
            }
            float mx[16];
            #pragma unroll
            for (int i = 0; i < 16; i++) mx[i] = fmaxf(vv[i], vv[i + 16]);
            #pragma unroll
            for (int off = 8; off; off >>= 1)
                #pragma unroll
                for (int i = 0; i < 8; i++)
                    if (i < off) mx[i] = fmaxf(mx[i], mx[i + off]);
            const float vmax = mx[0];
            unsigned eq = 0;
            #pragma unroll
            for (int h = 0; h < T; h++)
                if (vv[h] == vmax) eq |= (1u << h);
            const float pv = (float)(__ffs(eq) - 1);
            #pragma unroll 4
            for (int s = len; s < S; s++) { __stcs(pout, pv); pout += BT; }
        }

        // best_score = max(sc + t[STOP,:])
        float v = sc + tstop;
        #pragma unroll
        for (int o = 16; o; o >>= 1)
            v = fmaxf(v, __shfl_xor_sync(0xffffffffu, v, o));
        if (lane == 0) out[B + b] = v;
    }
}

extern "C" void kernel_launch(void* const* d_in, const int* in_sizes, int n_in,
                              void* d_out, int out_size) {
    const float* feats = (const float*)d_in[0];
    const float* mask  = (const float*)d_in[1];
    const float* trans = (const float*)d_in[2];
    crf_kernel<<<B, 64>>>(feats, mask, trans, (float*)d_out);
}

// round 17
// speedup vs baseline: 1.5099x; 1.5099x over previous
#include <cuda_runtime.h>
#include <cstdint>

// CRF forward (logZ) + Viterbi. KEY INSIGHT from R15/R16 profiles: warp->SMSP
// is wid%4 within a block, so 1-warp blocks used ONE SMSP/SM (issue capped
// ~43%) and 2-warp blocks TWO (~45%). This kernel: 4 warps/block covering
// all 4 SMSPs -- two batches per block (w0=fwdA, w1=vitA, w2=fwdB, w3=vitB).
// Per-warp scan bodies are verbatim R15/R16 (proven, rel_err 2.5e-6).
// out (f32): [0,B) logZ, [B,2B) best_score, [2B, 2B+S*B*T) pointers.

constexpr int S = 1024, B = 1024, T = 32;
#define NEG_INF   (-10000.0f)
#define START_TAG 29
#define STOP_TAG  30

__device__ __forceinline__ void ffma2(unsigned long long& d, unsigned long long a, unsigned long long b) {
    asm("fma.rn.f32x2 %0, %1, %2, %0;" : "+l"(d) : "l"(a), "l"(b));
}
__device__ __forceinline__ unsigned long long fadd2(unsigned long long a, unsigned long long b) {
    unsigned long long r;
    asm("add.rn.f32x2 %0, %1, %2;" : "=l"(r) : "l"(a), "l"(b));
    return r;
}
__device__ __forceinline__ unsigned long long pack2(float lo, float hi) {
    unsigned long long r;
    asm("mov.b64 %0, {%1, %2};" : "=l"(r) : "f"(lo), "f"(hi));
    return r;
}
__device__ __forceinline__ void unpack2(unsigned long long v, float& lo, float& hi) {
    asm("mov.b64 {%0, %1}, %2;" : "=f"(lo), "=f"(hi) : "l"(v));
}

__global__ void __launch_bounds__(128) crf_kernel(
    const float* __restrict__ feats, const float* __restrict__ mask,
    const float* __restrict__ trans, float* __restrict__ out)
{
    __shared__ __align__(16) float Eb[2][2][T];   // [batchInBlock][pb][lane]
    __shared__ __align__(16) float Sb[2][2][T];

    const int lane = threadIdx.x & 31;
    const int warp = threadIdx.x >> 5;
    const int role = warp & 1;          // 0 = forward, 1 = viterbi
    const int bb   = warp >> 1;         // batch-in-block (0/1)
    const int b    = blockIdx.x * 2 + bb;

    // length = first s with mask[s][b]==0 (mask monotone). One-time search.
    int lo = 0, hi = S;
    #pragma unroll 1
    while (lo < hi) {
        const int mid = (lo + hi) >> 1;
        if (__ldg(mask + (size_t)mid * B + b) != 0.0f) lo = mid + 1; else hi = mid;
    }
    const int len = lo;

    const float L2E = 1.4426950408889634f;
    const float LN2 = 0.6931471805599453f;
    const float tstop = __ldg(trans + STOP_TAG * T + lane);

    const size_t BT = (size_t)B * T;
    const float* fp = feats + (size_t)b * T + lane;

    // Depth-4 register prefetch ring.
    float fq[4];
    #pragma unroll
    for (int k = 0; k < 4; k++) fq[k] = __ldg(fp + (size_t)k * BT);

    if (role == 0) {
        // ================= Forward: log partition =================
        unsigned long long W2[T / 2];
        #pragma unroll
        for (int k = 0; k < T / 2; k++)
            W2[k] = pack2(__expf(__ldg(trans + lane * T + 2 * k)),
                          __expf(__ldg(trans + lane * T + 2 * k + 1)));

        float Ev = (lane == START_TAG) ? 1.0f : 0.0f;
        float O  = 0.0f;

        Eb[bb][0][lane] = Ev;
        __syncwarp();

        #pragma unroll 4
        for (int s = 0; s < len; s++) {
            const int j  = s & 3;
            const int pb = s & 1;
            const float fv = fq[j];
            const int pfr = (s + 4 < S) ? (s + 4) : (S - 1);
            fq[j] = __ldg(fp + (size_t)pfr * BT);

            float X;                                 // exp(feat) raw
            asm("ex2.approx.ftz.f32 %0, %1;" : "=f"(X) : "f"(fv * L2E));

            const ulonglong2* e2 = (const ulonglong2*)Eb[bb][pb];
            unsigned long long a0 = 0ull, a1 = 0ull, a2 = 0ull, a3 = 0ull;
            #pragma unroll
            for (int k = 0; k < 4; k++) {
                const ulonglong2 qa = e2[2 * k];
                const ulonglong2 qb = e2[2 * k + 1];
                ffma2(a0, qa.x, W2[4 * k]);
                ffma2(a1, qa.y, W2[4 * k + 1]);
                ffma2(a2, qb.x, W2[4 * k + 2]);
                ffma2(a3, qb.y, W2[4 * k + 3]);
            }
            const unsigned long long sAB = fadd2(fadd2(a0, a1), fadd2(a2, a3));
            float sl, sh; unpack2(sAB, sl, sh);
            const float sum = sl + sh;

            if (pb) {
                // Odd step: exact power-of-2 renorm off lane0's sum exponent.
                const int s0b = __shfl_sync(0xffffffffu, __float_as_int(sum), 0);
                const int e   = (s0b >> 23) - 127;
                const float g = __int_as_float((127 - e) << 23);  // exact 2^-e
                Ev = (sum * g) * X;
                O = fmaf((float)e, LN2, O);
            } else {
                Ev = sum * X;                        // no cross-lane traffic
            }

            Eb[bb][pb ^ 1][lane] = Ev;
            __syncwarp();
        }

        // logZ = O + log( sum_i E_i * exp(tstop_i) )
        float z = Ev * __expf(tstop);
        #pragma unroll
        for (int o = 16; o; o >>= 1)
            z += __shfl_xor_sync(0xffffffffu, z, o);
        if (lane == 0) out[b] = O + __logf(z);
    } else {
        // ================= Viterbi: max score + pointers =================
        unsigned long long T2[T / 2];
        #pragma unroll
        for (int k = 0; k < T / 2; k++)
            T2[k] = pack2(__ldg(trans + lane * T + 2 * k),
                          __ldg(trans + lane * T + 2 * k + 1));

        float sc = (lane == START_TAG) ? 0.0f : NEG_INF;
        Sb[bb][0][lane] = sc;
        __syncwarp();

        float* pout = out + 2 * B + (size_t)b * T + lane;

        #pragma unroll 4
        for (int s = 0; s < len; s++) {
            const int j  = s & 3;
            const int pb = s & 1;
            const float fv = fq[j];
            const int pfr = (s + 4 < S) ? (s + 4) : (S - 1);
            fq[j] = __ldg(fp + (size_t)pfr * BT);

            const ulonglong2* s2 = (const ulonglong2*)Sb[bb][pb];
            float vv[T];
            #pragma unroll
            for (int k = 0; k < 8; k++) {
                const ulonglong2 q = s2[k];
                float x0, x1, y0, y1;
                unpack2(fadd2(q.x, T2[2 * k]),     x0, x1);
                unpack2(fadd2(q.y, T2[2 * k + 1]), y0, y1);
                vv[4 * k]     = x0; vv[4 * k + 1] = x1;
                vv[4 * k + 2] = y0; vv[4 * k + 3] = y1;
            }
            float mx[16];
            #pragma unroll
            for (int i = 0; i < 16; i++) mx[i] = fmaxf(vv[i], vv[i + 16]);
            #pragma unroll
            for (int off = 8; off; off >>= 1)
                #pragma unroll
                for (int i = 0; i < 8; i++)
                    if (i < off) mx[i] = fmaxf(mx[i], mx[i + off]);
            const float vmax = mx[0];
            sc = vmax + fv;                          // exact update

            Sb[bb][pb ^ 1][lane] = sc;
            __syncwarp();

            // off-chain: EXACT first-index argmax + pointer store
            unsigned eq = 0;
            #pragma unroll
            for (int h = 0; h < T; h++)
                if (vv[h] == vmax) eq |= (1u << h);
            __stcs(pout, (float)(__ffs(eq) - 1));
            pout += BT;
        }

        if (len < S) {
            // Frozen scores: Sb[bb][len&1] holds final sc. Tail ptr constant.
            const ulonglong2* s2 = (const ulonglong2*)Sb[bb][len & 1];
            float vv[T];
            #pragma unroll
            for (int k = 0; k < 8; k++) {
                const ulonglong2 q = s2[k];
                float x0, x1, y0, y1;
                unpack2(fadd2(q.x, T2[2 * k]),     x0, x1);
                unpack2(fadd2(q.y, T2[2 * k + 1]), y0, y1);
                vv[4 * k]     = x0; vv[4 * k + 1] = x1;
                vv[4 * k + 2] = y0; vv[4 * k + 3] = y1;
            }
            float mx[16];
            #pragma unroll
            for (int i = 0; i < 16; i++) mx[i] = fmaxf(vv[i], vv[i + 16]);
            #pragma unroll
            for (int off = 8; off; off >>= 1)
                #pragma unroll
                for (int i = 0; i < 8; i++)
                    if (i < off) mx[i] = fmaxf(mx[i], mx[i + off]);
            const float vmax = mx[0];
            unsigned eq = 0;
            #pragma unroll
            for (int h = 0; h < T; h++)
                if (vv[h] == vmax) eq |= (1u << h);
            const float pv = (float)(__ffs(eq) - 1);
            #pragma unroll 4
            for (int s = len; s < S; s++) { __stcs(pout, pv); pout += BT; }
        }

        // best_score = max(sc + t[STOP,:])
        float v = sc + tstop;
        #pragma unroll
        for (int o = 16; o; o >>= 1)
            v = fmaxf(v, __shfl_xor_sync(0xffffffffu, v, o));
        if (lane == 0) out[B + b] = v;
    }
}

extern "C" void kernel_launch(void* const* d_in, const int* in_sizes, int n_in,
                              void* d_out, int out_size) {
    const float* feats = (const float*)d_in[0];
    const float* mask  = (const float*)d_in[1];
    const float* trans = (const float*)d_in[2];
    crf_kernel<<<B / 2, 128>>>(feats, mask, trans, (float*)d_out);
}